// round 2
// baseline (speedup 1.0000x reference)
#include <cuda_runtime.h>
#include <math.h>

#define Bn   64
#define Tn   512
#define NI   64
#define Hn   1024
#define THm  256     // T_HARM
#define TSp  256     // T_SPIKE
#define NCTA 128
#define DT_F 0.042f

// ---------------- device scratch (no allocations allowed) ----------------
__device__ float g_P[(size_t)Bn * THm * Hn];   // x[:, :256] @ x2h   (64 MB)
__device__ float g_hy[2][Bn * Hn];             // double-buffered recurrent state
__device__ float g_hyfin[Bn * Hn];
__device__ float g_hzfin[Bn * Hn];
__device__ float g_hyW[Bn * Hn];
__device__ unsigned g_count;
__device__ unsigned g_gen;

// ---------------- init ----------------
__global__ void init_kernel() {
    int idx = blockIdx.x * blockDim.x + threadIdx.x;
    if (idx < Bn * Hn) g_hy[0][idx] = 0.f;
    if (idx == 0) { g_count = 0u; g_gen = 0u; }
}

// ---------------- P = x[:, :256] @ x2h ----------------
__global__ void p_kernel(const float* __restrict__ x, const float* __restrict__ x2h) {
    __shared__ float xs[NI];
    int blk = blockIdx.x;            // 0 .. B*TH-1
    int b = blk >> 8;                // / 256
    int t = blk & 255;
    int row = b * Tn + t;            // row in x (B,T,NI)
    int tid = threadIdx.x;
    if (tid < NI) xs[tid] = x[row * NI + tid];
    __syncthreads();
    int h = tid * 4;
    float4 acc = make_float4(0.f, 0.f, 0.f, 0.f);
#pragma unroll 8
    for (int k = 0; k < NI; k++) {
        float xv = xs[k];
        float4 w = *reinterpret_cast<const float4*>(x2h + k * Hn + h);
        acc.x += xv * w.x; acc.y += xv * w.y; acc.z += xv * w.z; acc.w += xv * w.w;
    }
    *reinterpret_cast<float4*>(g_P + ((size_t)b * THm + t) * Hn + h) = acc;
}

// ---------------- grid-wide spin barrier (all 128 CTAs resident) ----------------
__device__ __forceinline__ void gsync() {
    __syncthreads();
    if (threadIdx.x == 0) {
        __threadfence();
        unsigned gen = *((volatile unsigned*)&g_gen);
        if (atomicAdd(&g_count, 1u) == NCTA - 1) {
            g_count = 0u;
            __threadfence();
            *((volatile unsigned*)&g_gen) = gen + 1u;
        } else {
            while (*((volatile unsigned*)&g_gen) == gen) { }
        }
    }
    __syncthreads();
}

// ---------------- harmonic persistent scan ----------------
// grid = 128 CTAs x 256 threads.  CTA tile: 32 h-cols (hb) x 16 batch rows (bb).
// thread: h = hb*32 + lane; owns 2 batch rows b0,b1.  hz kept in registers.
__global__ void __launch_bounds__(256, 1) harm_kernel(
    const float* __restrict__ h2h, const float* __restrict__ bias,
    const float* __restrict__ gvec, const float* __restrict__ evec,
    float* __restrict__ hys, float* __restrict__ hzs)
{
    extern __shared__ float hyS[];   // 16 * 1024 floats = 64 KB
    const int tid  = threadIdx.x;
    const int lane = tid & 31;
    const int wp   = tid >> 5;
    const int hb   = blockIdx.x & 31;
    const int bb   = blockIdx.x >> 5;
    const int h    = hb * 32 + lane;
    const int b0   = bb * 16 + 2 * wp;
    const int b1   = b0 + 1;

    const float gy = gvec[h];
    const float ge = evec[h];
    const float bi = bias[h];
    const float* Wc = h2h + h;   // column h, stride Hn over k

    float hy0 = 0.f, hy1 = 0.f, hz0 = 0.f, hz1 = 0.f;
    int cur = 0;

    const float4* r0v = reinterpret_cast<const float4*>(hyS + (2 * wp) * Hn);
    const float4* r1v = reinterpret_cast<const float4*>(hyS + (2 * wp + 1) * Hn);

    for (int t = 0; t < THm; t++) {
        float acc0 = 0.f, acc1 = 0.f;
        if (t > 0) {
            // stage this CTA's 16 batch rows of hy into smem (L2 reads: L1 is stale)
            const float4* src = reinterpret_cast<const float4*>(g_hy[cur] + bb * 16 * Hn);
#pragma unroll
            for (int i = 0; i < 16; i++)
                reinterpret_cast<float4*>(hyS)[tid + i * 256] = __ldcg(src + tid + i * 256);
            __syncthreads();
#pragma unroll 4
            for (int k4 = 0; k4 < Hn / 4; k4++) {
                float4 a = r0v[k4];
                float4 c = r1v[k4];
                int k = k4 * 4;
                float w0 = __ldg(Wc + (k + 0) * Hn);
                float w1 = __ldg(Wc + (k + 1) * Hn);
                float w2 = __ldg(Wc + (k + 2) * Hn);
                float w3 = __ldg(Wc + (k + 3) * Hn);
                acc0 += a.x * w0; acc1 += c.x * w0;
                acc0 += a.y * w1; acc1 += c.y * w1;
                acc0 += a.z * w2; acc1 += c.z * w2;
                acc0 += a.w * w3; acc1 += c.w * w3;
            }
        }
        float p0 = g_P[((size_t)b0 * THm + t) * Hn + h];
        float p1 = g_P[((size_t)b1 * THm + t) * Hn + h];
        float th0 = tanhf(acc0 + p0 + bi);
        float th1 = tanhf(acc1 + p1 + bi);
        hz0 = hz0 + DT_F * (th0 - gy * hy0 - ge * hz0);
        hy0 = hy0 + DT_F * hz0;
        hz1 = hz1 + DT_F * (th1 - gy * hy1 - ge * hz1);
        hy1 = hy1 + DT_F * hz1;

        int nxt = cur ^ 1;
        g_hy[nxt][b0 * Hn + h] = hy0;
        g_hy[nxt][b1 * Hn + h] = hy1;
        hys[((size_t)b0 * Tn + t) * Hn + h] = hy0;
        hys[((size_t)b1 * Tn + t) * Hn + h] = hy1;
        hzs[((size_t)b0 * Tn + t) * Hn + h] = hz0;
        hzs[((size_t)b1 * Tn + t) * Hn + h] = hz1;
        cur = nxt;
        gsync();
    }

    g_hyfin[b0 * Hn + h] = hy0;  g_hyfin[b1 * Hn + h] = hy1;
    g_hzfin[b0 * Hn + h] = hz0;  g_hzfin[b1 * Hn + h] = hz1;

    // hyW = hy_final @ h2h  (one more GEMM pass)
    {
        const float4* src = reinterpret_cast<const float4*>(g_hy[cur] + bb * 16 * Hn);
#pragma unroll
        for (int i = 0; i < 16; i++)
            reinterpret_cast<float4*>(hyS)[tid + i * 256] = __ldcg(src + tid + i * 256);
        __syncthreads();
        float acc0 = 0.f, acc1 = 0.f;
#pragma unroll 4
        for (int k4 = 0; k4 < Hn / 4; k4++) {
            float4 a = r0v[k4];
            float4 c = r1v[k4];
            int k = k4 * 4;
            float w0 = __ldg(Wc + (k + 0) * Hn);
            float w1 = __ldg(Wc + (k + 1) * Hn);
            float w2 = __ldg(Wc + (k + 2) * Hn);
            float w3 = __ldg(Wc + (k + 3) * Hn);
            acc0 += a.x * w0; acc1 += c.x * w0;
            acc0 += a.y * w1; acc1 += c.y * w1;
            acc0 += a.z * w2; acc1 += c.z * w2;
            acc0 += a.w * w3; acc1 += c.w * w3;
        }
        g_hyW[b0 * Hn + h] = acc0;
        g_hyW[b1 * Hn + h] = acc1;
    }
}

// ---------------- spiking phase + tail broadcast ----------------
__global__ void spike_kernel(float* __restrict__ out) {
    int idx = blockIdx.x * blockDim.x + threadIdx.x;   // 0 .. B*H-1
    int b = idx >> 10;
    int h = idx & 1023;

    float hyw = g_hyW[idx];
    float hyf = g_hyfin[idx];
    float hzf = g_hzfin[idx];
    float u = 0.f;

    float* hys = out;
    float* hzs = out + (size_t)Bn * Tn * Hn;
    float* us  = out + (size_t)2 * Bn * Tn * Hn;
    float* sp  = us  + (size_t)Bn * TSp * Hn;

    const float* Pb = g_P + (size_t)b * THm * Hn + h;
    size_t o_us = (size_t)b * TSp * Hn + h;
    size_t o_hy = ((size_t)b * Tn + THm) * Hn + h;

#pragma unroll 4
    for (int t = 0; t < TSp; t++) {
        float s = (u > 0.008f) ? 1.f : 0.f;
        if (s != 0.f) u = 0.001f;
        float p = Pb[(size_t)t * Hn];
        u = u + (-u + hyw + p) * 0.025f * 0.042f;   // (R*C) then *DT, as in ref
        us[o_us] = u;
        sp[o_us] = s;
        hys[o_hy] = hyf;
        hzs[o_hy] = hzf;
        o_us += Hn;
        o_hy += Hn;
    }
}

// ---------------- launch ----------------
extern "C" void kernel_launch(void* const* d_in, const int* in_sizes, int n_in,
                              void* d_out, int out_size) {
    const float* x    = (const float*)d_in[0];
    const float* x2h  = (const float*)d_in[1];
    const float* h2h  = (const float*)d_in[2];
    const float* bias = (const float*)d_in[3];
    const float* gvec = (const float*)d_in[4];
    const float* evec = (const float*)d_in[5];
    float* out = (float*)d_out;

    cudaFuncSetAttribute(harm_kernel, cudaFuncAttributeMaxDynamicSharedMemorySize,
                         16 * Hn * (int)sizeof(float));

    init_kernel<<<(Bn * Hn + 255) / 256, 256>>>();
    p_kernel<<<Bn * THm, 256>>>(x, x2h);
    harm_kernel<<<NCTA, 256, 16 * Hn * sizeof(float)>>>(
        h2h, bias, gvec, evec, out, out + (size_t)Bn * Tn * Hn);
    spike_kernel<<<Bn * Hn / 256, 256>>>(out);
}

// round 3
// speedup vs baseline: 1.1036x; 1.1036x over previous
#include <cuda_runtime.h>
#include <math.h>

#define Bn   64
#define Tn   512
#define NI   64
#define Hn   1024
#define THm  256     // T_HARM
#define TSp  256     // T_SPIKE
#define NCTA 128     // 32 h-groups x 4 batch-groups
#define DT_F 0.042f

// ---------------- device scratch (no allocations allowed) ----------------
__device__ float g_P[(size_t)Bn * THm * Hn];   // x[:, :256] @ x2h   (64 MB)
__device__ float g_hy[2][Bn * Hn];             // double-buffered recurrent state
__device__ float g_hyfin[Bn * Hn];
__device__ float g_hzfin[Bn * Hn];
__device__ float g_hyW[Bn * Hn];
__device__ unsigned g_count[4];
__device__ unsigned g_gen[4];

// ---------------- init ----------------
__global__ void init_kernel() {
    int idx = blockIdx.x * blockDim.x + threadIdx.x;
    if (idx < Bn * Hn) g_hy[0][idx] = 0.f;
    if (idx < 4) { g_count[idx] = 0u; g_gen[idx] = 0u; }
}

// ---------------- P = x[:, :256] @ x2h ----------------
__global__ void p_kernel(const float* __restrict__ x, const float* __restrict__ x2h) {
    __shared__ float xs[NI];
    int blk = blockIdx.x;            // 0 .. B*TH-1
    int b = blk >> 8;
    int t = blk & 255;
    int row = b * Tn + t;
    int tid = threadIdx.x;
    if (tid < NI) xs[tid] = x[row * NI + tid];
    __syncthreads();
    int h = tid * 4;
    float4 acc = make_float4(0.f, 0.f, 0.f, 0.f);
#pragma unroll 8
    for (int k = 0; k < NI; k++) {
        float xv = xs[k];
        float4 w = *reinterpret_cast<const float4*>(x2h + k * Hn + h);
        acc.x += xv * w.x; acc.y += xv * w.y; acc.z += xv * w.z; acc.w += xv * w.w;
    }
    *reinterpret_cast<float4*>(g_P + ((size_t)b * THm + t) * Hn + h) = acc;
}

// ---------------- 32-CTA group spin barrier ----------------
__device__ __forceinline__ void gsync(int grp) {
    __syncthreads();
    if (threadIdx.x == 0) {
        __threadfence();
        unsigned gen = *((volatile unsigned*)&g_gen[grp]);
        if (atomicAdd(&g_count[grp], 1u) == 31u) {
            g_count[grp] = 0u;
            __threadfence();
            *((volatile unsigned*)&g_gen[grp]) = gen + 1u;
        } else {
            while (*((volatile unsigned*)&g_gen[grp]) == gen) { __nanosleep(32); }
        }
    }
    __syncthreads();
}

// ---------------- harmonic persistent scan ----------------
// 128 CTAs x 256 threads.  CTA tile: 32 h-cols (hb) x 16 batch rows (bb).
// SMEM: W slice (transposed, [k4][lane] float4) 128 KB + hy rows 64 KB = 192 KB.
// Thread owns h = hb*32+lane, batches b0,b1; hz kept in registers.
__global__ void __launch_bounds__(256, 1) harm_kernel(
    const float* __restrict__ h2h, const float* __restrict__ bias,
    const float* __restrict__ gvec, const float* __restrict__ evec,
    float* __restrict__ hys, float* __restrict__ hzs)
{
    extern __shared__ float smem[];
    float* Wt  = smem;               // 32*1024 floats = 128 KB
    float* hyS = smem + 32 * Hn;     // 16*1024 floats = 64 KB

    const int tid  = threadIdx.x;
    const int lane = tid & 31;
    const int wp   = tid >> 5;
    const int hb   = blockIdx.x & 31;
    const int bb   = blockIdx.x >> 5;           // 0..3  (barrier group)
    const int h    = hb * 32 + lane;
    const int b0   = bb * 16 + 2 * wp;
    const int b1   = b0 + 1;

    // ---- stage this CTA's W column-slice into smem, transposed ----
    // Wt layout: word index (k>>2)*128 + lane*4 + (k&3)  -> LDS.128 at lane*16B: conflict-free
    {
        const float* Wg = h2h + hb * 32 + lane;  // column h, stride Hn over k
#pragma unroll 8
        for (int kk = 0; kk < 128; kk++) {
            int k = kk * 8 + wp;
            Wt[(k >> 2) * 128 + lane * 4 + (k & 3)] = Wg[(size_t)k * Hn];
        }
    }

    const float gy = gvec[h];
    const float ge = evec[h];
    const float bi = bias[h];

    float hy0 = 0.f, hy1 = 0.f, hz0 = 0.f, hz1 = 0.f;
    int cur = 0;

    const float4* r0v = reinterpret_cast<const float4*>(hyS + (2 * wp) * Hn);
    const float4* r1v = reinterpret_cast<const float4*>(hyS + (2 * wp + 1) * Hn);
    const float4* wv  = reinterpret_cast<const float4*>(Wt) + lane;   // + k4*32

    __syncthreads();

    for (int t = 0; t < THm; t++) {
        float p0 = g_P[((size_t)b0 * THm + t) * Hn + h];
        float p1 = g_P[((size_t)b1 * THm + t) * Hn + h];
        float acc0 = 0.f, acc1 = 0.f;
        if (t > 0) {
            // stage this group's 16 hy rows into smem (bypass stale L1)
            const float4* src = reinterpret_cast<const float4*>(g_hy[cur] + bb * 16 * Hn);
#pragma unroll
            for (int i = 0; i < 16; i++)
                reinterpret_cast<float4*>(hyS)[tid + i * 256] = __ldcg(src + tid + i * 256);
            __syncthreads();
#pragma unroll 4
            for (int k4 = 0; k4 < Hn / 4; k4++) {
                float4 w = wv[k4 * 32];
                float4 a = r0v[k4];
                float4 c = r1v[k4];
                acc0 += a.x * w.x; acc1 += c.x * w.x;
                acc0 += a.y * w.y; acc1 += c.y * w.y;
                acc0 += a.z * w.z; acc1 += c.z * w.z;
                acc0 += a.w * w.w; acc1 += c.w * w.w;
            }
        }
        float th0 = tanhf(acc0 + p0 + bi);
        float th1 = tanhf(acc1 + p1 + bi);
        hz0 = hz0 + DT_F * (th0 - gy * hy0 - ge * hz0);
        hy0 = hy0 + DT_F * hz0;
        hz1 = hz1 + DT_F * (th1 - gy * hy1 - ge * hz1);
        hy1 = hy1 + DT_F * hz1;

        int nxt = cur ^ 1;
        g_hy[nxt][b0 * Hn + h] = hy0;
        g_hy[nxt][b1 * Hn + h] = hy1;
        hys[((size_t)b0 * Tn + t) * Hn + h] = hy0;
        hys[((size_t)b1 * Tn + t) * Hn + h] = hy1;
        hzs[((size_t)b0 * Tn + t) * Hn + h] = hz0;
        hzs[((size_t)b1 * Tn + t) * Hn + h] = hz1;
        cur = nxt;
        gsync(bb);
    }

    g_hyfin[b0 * Hn + h] = hy0;  g_hyfin[b1 * Hn + h] = hy1;
    g_hzfin[b0 * Hn + h] = hz0;  g_hzfin[b1 * Hn + h] = hz1;

    // hyW = hy_final @ h2h (one more pass, same tiling)
    {
        const float4* src = reinterpret_cast<const float4*>(g_hy[cur] + bb * 16 * Hn);
#pragma unroll
        for (int i = 0; i < 16; i++)
            reinterpret_cast<float4*>(hyS)[tid + i * 256] = __ldcg(src + tid + i * 256);
        __syncthreads();
        float acc0 = 0.f, acc1 = 0.f;
#pragma unroll 4
        for (int k4 = 0; k4 < Hn / 4; k4++) {
            float4 w = wv[k4 * 32];
            float4 a = r0v[k4];
            float4 c = r1v[k4];
            acc0 += a.x * w.x; acc1 += c.x * w.x;
            acc0 += a.y * w.y; acc1 += c.y * w.y;
            acc0 += a.z * w.z; acc1 += c.z * w.z;
            acc0 += a.w * w.w; acc1 += c.w * w.w;
        }
        g_hyW[b0 * Hn + h] = acc0;
        g_hyW[b1 * Hn + h] = acc1;
    }
}

// ---------------- spiking phase + tail broadcast (float4 over h) ----------------
__global__ void spike_kernel(float* __restrict__ out) {
    int idx = blockIdx.x * blockDim.x + threadIdx.x;   // 0 .. B*H/4-1
    int b  = idx >> 8;             // / (1024/4)
    int h4 = (idx & 255) * 4;      // h base

    const float4* hyWv = reinterpret_cast<const float4*>(g_hyW);
    const float4* hyfv = reinterpret_cast<const float4*>(g_hyfin);
    const float4* hzfv = reinterpret_cast<const float4*>(g_hzfin);
    float4 hyw = hyWv[idx];
    float4 hyf = hyfv[idx];
    float4 hzf = hzfv[idx];
    float4 u = make_float4(0.f, 0.f, 0.f, 0.f);

    float* hys = out;
    float* hzs = out + (size_t)Bn * Tn * Hn;
    float* us  = out + (size_t)2 * Bn * Tn * Hn;
    float* sp  = us  + (size_t)Bn * TSp * Hn;

    const float* Pb = g_P + (size_t)b * THm * Hn + h4;
    size_t o_us = (size_t)b * TSp * Hn + h4;
    size_t o_hy = ((size_t)b * Tn + THm) * Hn + h4;
    const float k = 0.025f * 0.042f;   // (R*C)*DT as in reference

#pragma unroll 4
    for (int t = 0; t < TSp; t++) {
        float4 s;
        s.x = (u.x > 0.008f) ? 1.f : 0.f;  if (s.x != 0.f) u.x = 0.001f;
        s.y = (u.y > 0.008f) ? 1.f : 0.f;  if (s.y != 0.f) u.y = 0.001f;
        s.z = (u.z > 0.008f) ? 1.f : 0.f;  if (s.z != 0.f) u.z = 0.001f;
        s.w = (u.w > 0.008f) ? 1.f : 0.f;  if (s.w != 0.f) u.w = 0.001f;
        float4 p = *reinterpret_cast<const float4*>(Pb + (size_t)t * Hn);
        u.x += (-u.x + hyw.x + p.x) * k;
        u.y += (-u.y + hyw.y + p.y) * k;
        u.z += (-u.z + hyw.z + p.z) * k;
        u.w += (-u.w + hyw.w + p.w) * k;
        *reinterpret_cast<float4*>(us  + o_us) = u;
        *reinterpret_cast<float4*>(sp  + o_us) = s;
        *reinterpret_cast<float4*>(hys + o_hy) = hyf;
        *reinterpret_cast<float4*>(hzs + o_hy) = hzf;
        o_us += Hn;
        o_hy += Hn;
    }
}

// ---------------- launch ----------------
extern "C" void kernel_launch(void* const* d_in, const int* in_sizes, int n_in,
                              void* d_out, int out_size) {
    const float* x    = (const float*)d_in[0];
    const float* x2h  = (const float*)d_in[1];
    const float* h2h  = (const float*)d_in[2];
    const float* bias = (const float*)d_in[3];
    const float* gvec = (const float*)d_in[4];
    const float* evec = (const float*)d_in[5];
    float* out = (float*)d_out;

    const int smem_bytes = (32 * Hn + 16 * Hn) * (int)sizeof(float);  // 192 KB
    cudaFuncSetAttribute(harm_kernel, cudaFuncAttributeMaxDynamicSharedMemorySize,
                         smem_bytes);

    init_kernel<<<(Bn * Hn + 255) / 256, 256>>>();
    p_kernel<<<Bn * THm, 256>>>(x, x2h);
    harm_kernel<<<NCTA, 256, smem_bytes>>>(
        h2h, bias, gvec, evec, out, out + (size_t)Bn * Tn * Hn);
    spike_kernel<<<Bn * Hn / 4 / 256, 256>>>(out);
}

// round 4
// speedup vs baseline: 2.2133x; 2.0055x over previous
#include <cuda_runtime.h>
#include <math.h>

#define Bn   64
#define Tn   512
#define NI   64
#define Hn   1024
#define THm  256     // T_HARM
#define TSp  256     // T_SPIKE
#define NCTA 128     // 32 h-groups x 4 batch-groups
#define DT_F 0.042f

// packed fp32x2 helpers (FFMA2 — only reachable via PTX)
#define FMA2(acc, a, b) asm("fma.rn.f32x2 %0, %1, %2, %0;" : "+l"(acc) : "l"(a), "l"(b))
#define DUP2(d, f)      asm("mov.b64 %0, {%1, %1};" : "=l"(d) : "r"(__float_as_uint(f)))
#define UNPK2(lo, hi, v) asm("mov.b64 {%0, %1}, %2;" : "=f"(lo), "=f"(hi) : "l"(v))

// ---------------- device scratch ----------------
__device__ float g_P[(size_t)Bn * THm * Hn];   // x[:, :256] @ x2h  (64 MB)
__device__ float g_hy[2][Bn * Hn];             // double-buffered recurrent state
__device__ float g_hyfin[Bn * Hn];
__device__ float g_hzfin[Bn * Hn];
__device__ float g_hyW[Bn * Hn];
__device__ unsigned g_count[4];
__device__ unsigned g_gen[4];

// ---------------- init ----------------
__global__ void init_kernel() {
    int idx = blockIdx.x * blockDim.x + threadIdx.x;
    if (idx < Bn * Hn) g_hy[0][idx] = 0.f;
    if (idx < 4) { g_count[idx] = 0u; g_gen[idx] = 0u; }
}

// ---------------- P = x[:, :256] @ x2h ----------------
__global__ void p_kernel(const float* __restrict__ x, const float* __restrict__ x2h) {
    __shared__ float xs[NI];
    int blk = blockIdx.x;
    int b = blk >> 8;
    int t = blk & 255;
    int row = b * Tn + t;
    int tid = threadIdx.x;
    if (tid < NI) xs[tid] = x[row * NI + tid];
    __syncthreads();
    int h = tid * 4;
    float4 acc = make_float4(0.f, 0.f, 0.f, 0.f);
#pragma unroll 8
    for (int k = 0; k < NI; k++) {
        float xv = xs[k];
        float4 w = *reinterpret_cast<const float4*>(x2h + k * Hn + h);
        acc.x += xv * w.x; acc.y += xv * w.y; acc.z += xv * w.z; acc.w += xv * w.w;
    }
    *reinterpret_cast<float4*>(g_P + ((size_t)b * THm + t) * Hn + h) = acc;
}

// ---------------- 32-CTA group spin barrier ----------------
__device__ __forceinline__ void gsync(int grp) {
    __syncthreads();
    if (threadIdx.x == 0) {
        __threadfence();
        unsigned gen = *((volatile unsigned*)&g_gen[grp]);
        if (atomicAdd(&g_count[grp], 1u) == 31u) {
            g_count[grp] = 0u;
            __threadfence();
            *((volatile unsigned*)&g_gen[grp]) = gen + 1u;
        } else {
            while (*((volatile unsigned*)&g_gen[grp]) == gen) { __nanosleep(20); }
        }
    }
    __syncthreads();
}

// ---------------- harmonic persistent scan (split-K + FFMA2) ----------------
// 128 CTAs x 256 threads.  CTA tile: 32 h (hb) x 16 batches (bb).
// Warp wp: bg = wp&1 (which 8-batch half), kq = wp>>1 (k-quarter of 256).
// Thread: h = hb*32+lane; 4 batch-pair accumulators over its k-quarter.
// SMEM: Wt 128KB ([k4][lane][4], conflict-free) + hyP 64KB (float2[pair][k]) + red 8KB.
__global__ void __launch_bounds__(256, 1) harm_kernel(
    const float* __restrict__ h2h, const float* __restrict__ bias,
    const float* __restrict__ gvec, const float* __restrict__ evec,
    float* __restrict__ hys, float* __restrict__ hzs)
{
    extern __shared__ float smem[];
    float* Wt  = smem;                       // 32*1024 floats
    float* hyP = smem + 32 * Hn;             // 8 pairs * 1024 k * float2 = 16384 floats
    float* red = smem + 48 * Hn;             // 4kq * 2bg * 32lane * 4p * float2 = 2048 floats

    const int tid  = threadIdx.x;
    const int lane = tid & 31;
    const int wp   = tid >> 5;
    const int hb   = blockIdx.x & 31;
    const int bb   = blockIdx.x >> 5;         // barrier group
    const int h    = hb * 32 + lane;
    const int bg   = wp & 1;
    const int kq   = wp >> 1;

    // ---- stage W column-slice, transposed: Wt[(k>>2)*128 + lane*4 + (k&3)] ----
    {
        const float* Wg = h2h + hb * 32 + lane;
#pragma unroll 8
        for (int kk = 0; kk < 128; kk++) {
            int k = kk * 8 + wp;
            Wt[(k >> 2) * 128 + lane * 4 + (k & 3)] = Wg[(size_t)k * Hn];
        }
    }

    const float gy = gvec[h];
    const float ge = evec[h];
    const float bi = bias[h];

    // update-warp (wp<2) state: 8 batches each (local b = 8*wp + j)
    float hyr[8], hzr[8];
#pragma unroll
    for (int j = 0; j < 8; j++) { hyr[j] = 0.f; hzr[j] = 0.f; }

    int cur = 0;
    const ulonglong2* hv0 = reinterpret_cast<const ulonglong2*>(hyP) + (size_t)(bg * 4 + 0) * 512;
    const ulonglong2* hv1 = hv0 + 512;
    const ulonglong2* hv2 = hv1 + 512;
    const ulonglong2* hv3 = hv2 + 512;
    const float4* wv = reinterpret_cast<const float4*>(Wt) + lane;
    unsigned long long* redu = reinterpret_cast<unsigned long long*>(red);
    const int red_idx = ((kq * 2 + bg) * 32 + lane) * 4;

    __syncthreads();

    for (int t = 0; t < THm; t++) {
        // prefetch P for update warps (8 batches)
        float pv[8];
        if (wp < 2) {
#pragma unroll
            for (int j = 0; j < 8; j++) {
                int b = bb * 16 + 8 * wp + j;
                pv[j] = g_P[((size_t)b * THm + t) * Hn + h];
            }
        }

        if (t > 0) {
            // ---- stage hy into pair layout: warp wp handles pair wp ----
            {
                const float4* r0 = reinterpret_cast<const float4*>(g_hy[cur] + (bb * 16 + 2 * wp) * Hn);
                const float4* r1 = r0 + Hn / 4;
                float4* dst = reinterpret_cast<float4*>(hyP + (size_t)wp * 2048);
#pragma unroll
                for (int i = 0; i < 8; i++) {
                    float4 a = __ldcg(r0 + lane + i * 32);
                    float4 b = __ldcg(r1 + lane + i * 32);
                    int k2 = (lane + i * 32) * 2;          // float4 index into pair row
                    dst[k2]     = make_float4(a.x, b.x, a.y, b.y);
                    dst[k2 + 1] = make_float4(a.z, b.z, a.w, b.w);
                }
            }
            __syncthreads();

            // ---- GEMM quarter-k: 4 pair accumulators ----
            unsigned long long acc0 = 0ull, acc1 = 0ull, acc2 = 0ull, acc3 = 0ull;
            const int k4e = kq * 64 + 64;
#pragma unroll 4
            for (int k4 = kq * 64; k4 < k4e; k4++) {
                float4 w = wv[k4 * 32];
                unsigned long long wx, wy, wz, ww;
                DUP2(wx, w.x); DUP2(wy, w.y); DUP2(wz, w.z); DUP2(ww, w.w);
                ulonglong2 a0 = hv0[2 * k4], b0 = hv0[2 * k4 + 1];
                ulonglong2 a1 = hv1[2 * k4], b1 = hv1[2 * k4 + 1];
                ulonglong2 a2 = hv2[2 * k4], b2 = hv2[2 * k4 + 1];
                ulonglong2 a3 = hv3[2 * k4], b3 = hv3[2 * k4 + 1];
                FMA2(acc0, a0.x, wx); FMA2(acc0, a0.y, wy); FMA2(acc0, b0.x, wz); FMA2(acc0, b0.y, ww);
                FMA2(acc1, a1.x, wx); FMA2(acc1, a1.y, wy); FMA2(acc1, b1.x, wz); FMA2(acc1, b1.y, ww);
                FMA2(acc2, a2.x, wx); FMA2(acc2, a2.y, wy); FMA2(acc2, b2.x, wz); FMA2(acc2, b2.y, ww);
                FMA2(acc3, a3.x, wx); FMA2(acc3, a3.y, wy); FMA2(acc3, b3.x, wz); FMA2(acc3, b3.y, ww);
            }
            redu[red_idx + 0] = acc0;
            redu[red_idx + 1] = acc1;
            redu[red_idx + 2] = acc2;
            redu[red_idx + 3] = acc3;
        }
        __syncthreads();

        // ---- reduce + state update: warps 0,1 only ----
        if (wp < 2) {
            float a[8];
#pragma unroll
            for (int j = 0; j < 8; j++) a[j] = 0.f;
            if (t > 0) {
                const float2* rv = reinterpret_cast<const float2*>(red);
#pragma unroll
                for (int q = 0; q < 4; q++) {
                    int base = ((q * 2 + wp) * 32 + lane) * 4;
#pragma unroll
                    for (int p = 0; p < 4; p++) {
                        float2 v = rv[base + p];
                        a[2 * p]     += v.x;
                        a[2 * p + 1] += v.y;
                    }
                }
            }
            int nxt = cur ^ 1;
#pragma unroll
            for (int j = 0; j < 8; j++) {
                float th = tanhf(a[j] + pv[j] + bi);
                hzr[j] = hzr[j] + DT_F * (th - gy * hyr[j] - ge * hzr[j]);
                hyr[j] = hyr[j] + DT_F * hzr[j];
                int b = bb * 16 + 8 * wp + j;
                g_hy[nxt][b * Hn + h] = hyr[j];
            }
            __threadfence();   // recurrent state visible before barrier release
#pragma unroll
            for (int j = 0; j < 8; j++) {
                int b = bb * 16 + 8 * wp + j;
                hys[((size_t)b * Tn + t) * Hn + h] = hyr[j];
                hzs[((size_t)b * Tn + t) * Hn + h] = hzr[j];
            }
        }
        cur ^= 1;
        gsync(bb);
    }

    // ---- final: hyfin/hzfin + hyW = hy_fin @ W (same machinery, no update) ----
    if (wp < 2) {
#pragma unroll
        for (int j = 0; j < 8; j++) {
            int b = bb * 16 + 8 * wp + j;
            g_hyfin[b * Hn + h] = hyr[j];
            g_hzfin[b * Hn + h] = hzr[j];
        }
    }
    {
        const float4* r0 = reinterpret_cast<const float4*>(g_hy[cur] + (bb * 16 + 2 * wp) * Hn);
        const float4* r1 = r0 + Hn / 4;
        float4* dst = reinterpret_cast<float4*>(hyP + (size_t)wp * 2048);
#pragma unroll
        for (int i = 0; i < 8; i++) {
            float4 a = __ldcg(r0 + lane + i * 32);
            float4 b = __ldcg(r1 + lane + i * 32);
            int k2 = (lane + i * 32) * 2;
            dst[k2]     = make_float4(a.x, b.x, a.y, b.y);
            dst[k2 + 1] = make_float4(a.z, b.z, a.w, b.w);
        }
    }
    __syncthreads();
    {
        unsigned long long acc0 = 0ull, acc1 = 0ull, acc2 = 0ull, acc3 = 0ull;
        const int k4e = kq * 64 + 64;
#pragma unroll 4
        for (int k4 = kq * 64; k4 < k4e; k4++) {
            float4 w = wv[k4 * 32];
            unsigned long long wx, wy, wz, ww;
            DUP2(wx, w.x); DUP2(wy, w.y); DUP2(wz, w.z); DUP2(ww, w.w);
            ulonglong2 a0 = hv0[2 * k4], b0 = hv0[2 * k4 + 1];
            ulonglong2 a1 = hv1[2 * k4], b1 = hv1[2 * k4 + 1];
            ulonglong2 a2 = hv2[2 * k4], b2 = hv2[2 * k4 + 1];
            ulonglong2 a3 = hv3[2 * k4], b3 = hv3[2 * k4 + 1];
            FMA2(acc0, a0.x, wx); FMA2(acc0, a0.y, wy); FMA2(acc0, b0.x, wz); FMA2(acc0, b0.y, ww);
            FMA2(acc1, a1.x, wx); FMA2(acc1, a1.y, wy); FMA2(acc1, b1.x, wz); FMA2(acc1, b1.y, ww);
            FMA2(acc2, a2.x, wx); FMA2(acc2, a2.y, wy); FMA2(acc2, b2.x, wz); FMA2(acc2, b2.y, ww);
            FMA2(acc3, a3.x, wx); FMA2(acc3, a3.y, wy); FMA2(acc3, b3.x, wz); FMA2(acc3, b3.y, ww);
        }
        redu[red_idx + 0] = acc0;
        redu[red_idx + 1] = acc1;
        redu[red_idx + 2] = acc2;
        redu[red_idx + 3] = acc3;
    }
    __syncthreads();
    if (wp < 2) {
        const float2* rv = reinterpret_cast<const float2*>(red);
        float a[8];
#pragma unroll
        for (int j = 0; j < 8; j++) a[j] = 0.f;
#pragma unroll
        for (int q = 0; q < 4; q++) {
            int base = ((q * 2 + wp) * 32 + lane) * 4;
#pragma unroll
            for (int p = 0; p < 4; p++) {
                float2 v = rv[base + p];
                a[2 * p]     += v.x;
                a[2 * p + 1] += v.y;
            }
        }
#pragma unroll
        for (int j = 0; j < 8; j++) {
            int b = bb * 16 + 8 * wp + j;
            g_hyW[b * Hn + h] = a[j];
        }
    }
}

// ---------------- spiking phase + tail broadcast (float4, 128 CTAs) ----------------
__global__ void spike_kernel(float* __restrict__ out) {
    int idx = blockIdx.x * blockDim.x + threadIdx.x;   // 0 .. B*H/4-1
    int b  = idx >> 8;
    int h4 = (idx & 255) * 4;

    float4 hyw = reinterpret_cast<const float4*>(g_hyW)[idx];
    float4 hyf = reinterpret_cast<const float4*>(g_hyfin)[idx];
    float4 hzf = reinterpret_cast<const float4*>(g_hzfin)[idx];
    float4 u = make_float4(0.f, 0.f, 0.f, 0.f);

    float* hys = out;
    float* hzs = out + (size_t)Bn * Tn * Hn;
    float* us  = out + (size_t)2 * Bn * Tn * Hn;
    float* sp  = us  + (size_t)Bn * TSp * Hn;

    const float* Pb = g_P + (size_t)b * THm * Hn + h4;
    size_t o_us = (size_t)b * TSp * Hn + h4;
    size_t o_hy = ((size_t)b * Tn + THm) * Hn + h4;
    const float k = 0.025f * 0.042f;

#pragma unroll 4
    for (int t = 0; t < TSp; t++) {
        float4 s;
        s.x = (u.x > 0.008f) ? 1.f : 0.f;  if (s.x != 0.f) u.x = 0.001f;
        s.y = (u.y > 0.008f) ? 1.f : 0.f;  if (s.y != 0.f) u.y = 0.001f;
        s.z = (u.z > 0.008f) ? 1.f : 0.f;  if (s.z != 0.f) u.z = 0.001f;
        s.w = (u.w > 0.008f) ? 1.f : 0.f;  if (s.w != 0.f) u.w = 0.001f;
        float4 p = *reinterpret_cast<const float4*>(Pb + (size_t)t * Hn);
        u.x += (-u.x + hyw.x + p.x) * k;
        u.y += (-u.y + hyw.y + p.y) * k;
        u.z += (-u.z + hyw.z + p.z) * k;
        u.w += (-u.w + hyw.w + p.w) * k;
        *reinterpret_cast<float4*>(us  + o_us) = u;
        *reinterpret_cast<float4*>(sp  + o_us) = s;
        *reinterpret_cast<float4*>(hys + o_hy) = hyf;
        *reinterpret_cast<float4*>(hzs + o_hy) = hzf;
        o_us += Hn;
        o_hy += Hn;
    }
}

// ---------------- launch ----------------
extern "C" void kernel_launch(void* const* d_in, const int* in_sizes, int n_in,
                              void* d_out, int out_size) {
    const float* x    = (const float*)d_in[0];
    const float* x2h  = (const float*)d_in[1];
    const float* h2h  = (const float*)d_in[2];
    const float* bias = (const float*)d_in[3];
    const float* gvec = (const float*)d_in[4];
    const float* evec = (const float*)d_in[5];
    float* out = (float*)d_out;

    const int smem_bytes = 50 * Hn * (int)sizeof(float);  // 200 KB
    cudaFuncSetAttribute(harm_kernel, cudaFuncAttributeMaxDynamicSharedMemorySize,
                         smem_bytes);

    init_kernel<<<(Bn * Hn + 255) / 256, 256>>>();
    p_kernel<<<Bn * THm, 256>>>(x, x2h);
    harm_kernel<<<NCTA, 256, smem_bytes>>>(
        h2h, bias, gvec, evec, out, out + (size_t)Bn * Tn * Hn);
    spike_kernel<<<Bn * Hn / 4 / 128, 128>>>(out);
}